// round 15
// baseline (speedup 1.0000x reference)
#include <cuda_runtime.h>
#include <cstdint>
#include <math.h>

#define Bq     16
#define Cq     256
#define HWq    16384
#define INTERq 128
#define CHUNKS 128

// scratch
__device__ float g_csum[Bq * CHUNKS * Cq];  // [b][chunk][c] (2 MB)
__device__ float g_pt  [Cq * Bq];           // pooled means [c][b]
__device__ float g_gtp [384 * Bq];          // proj outputs [col][b]: g|theta|phi
__device__ float g_wyt [Cq * Bq];           // pre-BN activations [c][b]
__device__ int   g_idx [Bq * 3];
__device__ int   g_c1, g_c2, g_c3, g_c4;    // phase counters

__device__ __forceinline__ float gelu_exact(float v) {
    return 0.5f * v * (1.0f + erff(v * 0.70710678118654752f));
}

// ---------------------------------------------------------------------------
// K1 (R4-exact, proven 45.6us @ 75.8% DRAM). Block 0 resets phase counters.
// ---------------------------------------------------------------------------
__global__ __launch_bounds__(256) void k1_stream(const float* __restrict__ x,
                                                 const float* __restrict__ W3,
                                                 float* __restrict__ out) {
    __shared__ float sw[Cq];
    __shared__ float scs[Cq][8];
    __shared__ float sdot[4][32][32];

    if (blockIdx.x == 0 && threadIdx.x == 0) { g_c1 = 0; g_c2 = 0; g_c3 = 0; g_c4 = 0; }

    const int b     = blockIdx.x >> 7;
    const int chunk = blockIdx.x & 127;
    const int t  = threadIdx.x;
    const int cw = t >> 3;
    const int pw = t & 7;

    for (int i = t; i < Cq; i += 256) sw[i] = W3[i];
    __syncthreads();

    const float* xb = x + ((size_t)b * Cq + (size_t)cw * 8) * HWq
                        + (size_t)chunk * 128 + (size_t)pw * 4;

    float4 dot[4];
    #pragma unroll
    for (int s = 0; s < 4; ++s) dot[s] = make_float4(0.f, 0.f, 0.f, 0.f);
    float cs[8];
    #pragma unroll
    for (int j = 0; j < 8; ++j) cs[j] = 0.f;

    #pragma unroll
    for (int j = 0; j < 8; ++j) {
        const float w = sw[cw * 8 + j];
        const float* xc = xb + (size_t)j * HWq;
        #pragma unroll
        for (int s = 0; s < 4; ++s) {
            const float4 v = *reinterpret_cast<const float4*>(xc + s * 32);
            dot[s].x = fmaf(v.x, w, dot[s].x);
            dot[s].y = fmaf(v.y, w, dot[s].y);
            dot[s].z = fmaf(v.z, w, dot[s].z);
            dot[s].w = fmaf(v.w, w, dot[s].w);
            cs[j] += (v.x + v.y) + (v.z + v.w);
        }
    }

    #pragma unroll
    for (int j = 0; j < 8; ++j) scs[cw * 8 + j][pw] = cs[j];
    #pragma unroll
    for (int s = 0; s < 4; ++s)
        *reinterpret_cast<float4*>(&sdot[s][cw][pw * 4]) = dot[s];
    __syncthreads();

    {
        float s = 0.f;
        #pragma unroll
        for (int k = 0; k < 8; ++k) s += scs[t][k];
        g_csum[((size_t)b * CHUNKS + chunk) * Cq + t] = s;
    }

    if (t < 128) {
        const int s = t >> 5, q = t & 31;
        float d = 0.f;
        #pragma unroll
        for (int k = 0; k < 32; ++k) d += sdot[s][k][q];
        out[(size_t)b * 4 * HWq + (size_t)chunk * 128 + t] = gelu_exact(d);
    }
}

// ---------------------------------------------------------------------------
// KSMALL: entire post-K1 chain, persistent. 48 blocks x 1024 threads.
//   phase1 pool (blocks 0..15) -> sync -> phase2 proj (0..23, t<256) -> sync
//   -> phase3 wy (0..15, t<256) -> sync -> phase4 BN+top3 (block 0) -> sync
//   -> phase5 gather (all 48 x 1024).
// ---------------------------------------------------------------------------
__device__ __forceinline__ void grid_arrive(int* ctr, bool producer) {
    __syncthreads();
    __threadfence();
    if (threadIdx.x == 0 && producer) atomicAdd(ctr, 1);
}
__device__ __forceinline__ void grid_wait(int* ctr, int target) {
    if (threadIdx.x == 0) {
        while (atomicAdd(ctr, 0) < target) { __nanosleep(32); }
        __threadfence();
    }
    __syncthreads();
}

__global__ __launch_bounds__(1024) void ksmall(
    const float* __restrict__ x,
    const float* __restrict__ Wg, const float* __restrict__ bg,
    const float* __restrict__ Wt, const float* __restrict__ bt,
    const float* __restrict__ Wp, const float* __restrict__ bp,
    const float* __restrict__ Wf, const float* __restrict__ bf,
    const float* __restrict__ Wz, const float* __restrict__ bz,
    const float* __restrict__ gamma, const float* __restrict__ beta,
    float* __restrict__ out)
{
    __shared__ float sm[9216];   // 36 KB, aliased per phase

    const int bid = blockIdx.x;
    const int t   = threadIdx.x;

    // ---------------- phase 1: pool (blocks 0..15, 1024 threads) -------------
    if (bid < Bq) {
        float* part = sm;                       // [4][256]
        const int c  = t & 255;
        const int qq = t >> 8;
        const float* cs = g_csum + (size_t)bid * CHUNKS * Cq + (size_t)qq * 32 * Cq + c;
        float s = 0.f;
        #pragma unroll 8
        for (int k = 0; k < 32; ++k) s += cs[(size_t)k * Cq];
        part[qq * 256 + c] = s;
        __syncthreads();
        if (t < Cq)
            g_pt[t * Bq + bid] = ((part[0 * 256 + t] + part[1 * 256 + t])
                                + (part[2 * 256 + t] + part[3 * 256 + t]))
                               * (1.0f / (float)HWq);
    }
    grid_arrive(&g_c1, bid < Bq);
    grid_wait(&g_c1, Bq);

    // ---------------- phase 2: proj (blocks 0..23, t<256) --------------------
    if (bid < 24) {
        float* sp_t = sm;            // 4096
        float* swt  = sm + 4096;     // 16*256
        float* sb   = sm + 8192;     // 16
        const int col0 = bid * 16;
        if (t < 256) {
            #pragma unroll
            for (int j = 0; j < 4; ++j)
                reinterpret_cast<float4*>(sp_t)[j * 256 + t] =
                    reinterpret_cast<const float4*>(g_pt)[j * 256 + t];
            #pragma unroll
            for (int j = 0; j < 4; ++j) {
                const int id = j * 256 + t;
                const int r  = id >> 6;
                const int c4 = id & 63;
                const int col = col0 + r;
                const int cg  = col >> 7;
                const int lc  = col & 127;
                const float* Wrow = (cg == 0) ? (Wg + (size_t)lc * Cq)
                                  : (cg == 1) ? (Wt + (size_t)lc * Cq)
                                              : (Wp + (size_t)lc * Cq);
                reinterpret_cast<float4*>(swt + r * 256)[c4] =
                    reinterpret_cast<const float4*>(Wrow)[c4];
            }
            if (t < 16) {
                const int col = col0 + t;
                const int cg  = col >> 7;
                const int lc  = col & 127;
                sb[t] = (cg == 0) ? bg[lc] : (cg == 1) ? bt[lc] : bp[lc];
            }
        }
        __syncthreads();
        if (t < 256) {
            const int b    = t & 15;
            const int slot = t >> 4;
            float a0 = 0.f, a1 = 0.f, a2 = 0.f, a3 = 0.f;
            #pragma unroll 8
            for (int i = 0; i < Cq; i += 4) {
                a0 = fmaf(swt[slot * 256 + i + 0], sp_t[(i + 0) * Bq + b], a0);
                a1 = fmaf(swt[slot * 256 + i + 1], sp_t[(i + 1) * Bq + b], a1);
                a2 = fmaf(swt[slot * 256 + i + 2], sp_t[(i + 2) * Bq + b], a2);
                a3 = fmaf(swt[slot * 256 + i + 3], sp_t[(i + 3) * Bq + b], a3);
            }
            g_gtp[(col0 + slot) * Bq + b] = ((a0 + a1) + (a2 + a3)) + sb[slot];
        }
    }
    grid_arrive(&g_c2, bid < 24);
    grid_wait(&g_c2, 24);

    // ---------------- phase 3: wy (blocks 0..15, t<256) ----------------------
    if (bid < Bq) {
        float* sg_t = sm;            // 2048
        float* stp  = sm + 2048;     // 4096
        float* swz  = sm + 6144;     // 2048
        float* swf  = sm + 8192;     // 256
        float* sfp  = sm + 8448;     // 256 [slot][b]
        float* sf   = sm + 8704;     // 16
        float* sbz  = sm + 8720;     // 16
        const int col0 = bid * 16;
        const int b    = t & 15;
        const int slot = t >> 4;
        if (t < 256) {
            #pragma unroll
            for (int j = 0; j < 2; ++j)
                reinterpret_cast<float4*>(sg_t)[j * 256 + t] =
                    reinterpret_cast<const float4*>(g_gtp)[j * 256 + t];
            #pragma unroll
            for (int j = 0; j < 4; ++j)
                reinterpret_cast<float4*>(stp)[j * 256 + t] =
                    reinterpret_cast<const float4*>(g_gtp + 2048)[j * 256 + t];
            #pragma unroll
            for (int j = 0; j < 2; ++j) {
                const int id = j * 256 + t;
                const int r  = id >> 5;
                const int c4 = id & 31;
                reinterpret_cast<float4*>(swz + r * 128)[c4] =
                    reinterpret_cast<const float4*>(Wz + (size_t)(col0 + r) * INTERq)[c4];
            }
            swf[t] = Wf[t];
            if (t < 16) sbz[t] = bz[col0 + t];
        }
        __syncthreads();
        if (t < 256) {
            float a = 0.f;
            #pragma unroll
            for (int i = 0; i < 16; ++i) {
                const int e = slot * 16 + i;
                a = fmaf(stp[e * Bq + b], swf[e], a);
            }
            sfp[slot * 16 + b] = a;
        }
        __syncthreads();
        if (t < 16) {
            float s0 = 0.f, s1 = 0.f;
            #pragma unroll
            for (int k = 0; k < 16; k += 2) { s0 += sfp[k * 16 + t]; s1 += sfp[(k + 1) * 16 + t]; }
            sf[t] = fmaxf(s0 + s1 + bf[0], 0.f);
        }
        __syncthreads();
        if (t < 256) {
            float a0 = 0.f, a1 = 0.f, a2 = 0.f, a3 = 0.f;
            #pragma unroll 8
            for (int i = 0; i < INTERq; i += 4) {
                a0 = fmaf(swz[slot * 128 + i + 0], sg_t[(i + 0) * Bq + b], a0);
                a1 = fmaf(swz[slot * 128 + i + 1], sg_t[(i + 1) * Bq + b], a1);
                a2 = fmaf(swz[slot * 128 + i + 2], sg_t[(i + 2) * Bq + b], a2);
                a3 = fmaf(swz[slot * 128 + i + 3], sg_t[(i + 3) * Bq + b], a3);
            }
            g_wyt[(col0 + slot) * Bq + b] = fmaf(sf[b], ((a0 + a1) + (a2 + a3)), sbz[slot]);
        }
    }
    grid_arrive(&g_c3, bid < Bq);
    grid_wait(&g_c3, Bq);

    // ---------------- phase 4: BN + top-3 (block 0) --------------------------
    if (bid == 0) {
        float* sz = sm;   // [b][c] 4096
        if (t < Cq) {
            const int c = t;
            float vals[Bq];
            const float4* w4 = reinterpret_cast<const float4*>(g_wyt + c * Bq);
            const float4* p4 = reinterpret_cast<const float4*>(g_pt  + c * Bq);
            #pragma unroll
            for (int k = 0; k < 4; ++k) {
                const float4 v = w4[k];
                vals[k * 4 + 0] = v.x; vals[k * 4 + 1] = v.y;
                vals[k * 4 + 2] = v.z; vals[k * 4 + 3] = v.w;
            }
            float m = 0.f;
            #pragma unroll
            for (int bb = 0; bb < Bq; ++bb) m += vals[bb];
            m *= (1.0f / (float)Bq);
            float var = 0.f;
            #pragma unroll
            for (int bb = 0; bb < Bq; ++bb) { const float d = vals[bb] - m; var = fmaf(d, d, var); }
            var *= (1.0f / (float)Bq);
            const float inv = rsqrtf(var + 1e-5f);
            const float ga = gamma[c], be = beta[c];
            #pragma unroll
            for (int k = 0; k < 4; ++k) {
                const float4 p = p4[k];
                sz[(k * 4 + 0) * Cq + c] = fmaf(ga * (vals[k * 4 + 0] - m), inv, be) + p.x;
                sz[(k * 4 + 1) * Cq + c] = fmaf(ga * (vals[k * 4 + 1] - m), inv, be) + p.y;
                sz[(k * 4 + 2) * Cq + c] = fmaf(ga * (vals[k * 4 + 2] - m), inv, be) + p.z;
                sz[(k * 4 + 3) * Cq + c] = fmaf(ga * (vals[k * 4 + 3] - m), inv, be) + p.w;
            }
        }
        __syncthreads();
        if (t < 512) {
            const int warp = t >> 5;   // 16 warps = 16 samples
            const int lane = t & 31;
            float v[8];
            const int base = warp * Cq;
            #pragma unroll
            for (int k = 0; k < 8; ++k) v[k] = sz[base + k * 32 + lane];

            for (int j = 0; j < 3; ++j) {
                float bv = -INFINITY;
                int   bi = 0x7fffffff;
                #pragma unroll
                for (int k = 0; k < 8; ++k) {
                    const int idx = k * 32 + lane;
                    if (v[k] > bv) { bv = v[k]; bi = idx; }
                }
                #pragma unroll
                for (int off = 16; off > 0; off >>= 1) {
                    const float ov = __shfl_down_sync(0xffffffffu, bv, off);
                    const int   oi = __shfl_down_sync(0xffffffffu, bi, off);
                    if (ov > bv || (ov == bv && oi < bi)) { bv = ov; bi = oi; }
                }
                bi = __shfl_sync(0xffffffffu, bi, 0);
                if (lane == 0) g_idx[warp * 3 + j] = bi;
                const int kk = bi >> 5;
                if ((bi & 31) == lane) {
                    #pragma unroll
                    for (int k = 0; k < 8; ++k) if (k == kk) v[k] = -INFINITY;
                }
            }
        }
    }
    grid_arrive(&g_c4, bid == 0);
    grid_wait(&g_c4, 1);

    // ---------------- phase 5: gather (all 48 blocks x 1024) -----------------
    {
        const int b = bid / 3, j = bid % 3;
        const int ch = g_idx[b * 3 + j];
        const float* src = x + ((size_t)b * Cq + ch) * HWq;
        float* dst = out + ((size_t)b * 4 + 1 + j) * HWq;
        const float4 v0 = *reinterpret_cast<const float4*>(src + t * 4);
        const float4 v1 = *reinterpret_cast<const float4*>(src + 4096 + t * 4);
        const float4 v2 = *reinterpret_cast<const float4*>(src + 8192 + t * 4);
        const float4 v3 = *reinterpret_cast<const float4*>(src + 12288 + t * 4);
        *reinterpret_cast<float4*>(dst + t * 4)         = v0;
        *reinterpret_cast<float4*>(dst + 4096 + t * 4)  = v1;
        *reinterpret_cast<float4*>(dst + 8192 + t * 4)  = v2;
        *reinterpret_cast<float4*>(dst + 12288 + t * 4) = v3;
    }
}

extern "C" void kernel_launch(void* const* d_in, const int* in_sizes, int n_in,
                              void* d_out, int out_size) {
    const float* x     = (const float*)d_in[0];
    const float* Wg    = (const float*)d_in[1];
    const float* bg    = (const float*)d_in[2];
    const float* Wt    = (const float*)d_in[3];
    const float* bt    = (const float*)d_in[4];
    const float* Wp    = (const float*)d_in[5];
    const float* bp    = (const float*)d_in[6];
    const float* Wf    = (const float*)d_in[7];
    const float* bf    = (const float*)d_in[8];
    const float* Wz    = (const float*)d_in[9];
    const float* bz    = (const float*)d_in[10];
    const float* gamma = (const float*)d_in[11];
    const float* beta  = (const float*)d_in[12];
    const float* W3    = (const float*)d_in[13];
    float* out = (float*)d_out;

    k1_stream<<<Bq * CHUNKS, 256>>>(x, W3, out);
    ksmall<<<48, 1024>>>(x, Wg, bg, Wt, bt, Wp, bp, Wf, bf,
                         Wz, bz, gamma, beta, out);
}